// round 1
// baseline (speedup 1.0000x reference)
#include <cuda_runtime.h>

#define BATCH 4
#define CIN   3
#define C1    32
#define C2    64
#define MROWS 512

// Intermediates (no allocation allowed -> __device__ globals)
__device__ float g_z1[BATCH * C1 * 16 * 16];   // conv1 output, relu'd
__device__ float g_z2[BATCH * C2 * 8 * 8];     // conv2 output, relu'd  == z_q_masked
__device__ float g_V [MROWS * C2];             // lookup @ Wv

// ---------------------------------------------------------------------------
// conv1: x (B,3,32,32) -> z1 (B,32,16,16), k=4, stride=2, pad=1, relu
// grid = B*C1 blocks, 256 threads (one per output pixel)
// ---------------------------------------------------------------------------
__global__ void conv1_kernel(const float* __restrict__ x,
                             const float* __restrict__ w,
                             const float* __restrict__ bias) {
    int blk = blockIdx.x;
    int b  = blk / C1;
    int oc = blk % C1;
    int t  = threadIdx.x;            // 0..255
    int oh = t >> 4, ow = t & 15;

    __shared__ float sw[CIN * 16];   // 48 weights for this oc
    if (t < CIN * 16) sw[t] = w[oc * CIN * 16 + t];
    __syncthreads();

    float acc = bias[oc];
    #pragma unroll
    for (int ic = 0; ic < CIN; ic++) {
        const float* xp = x + (b * CIN + ic) * 32 * 32;
        #pragma unroll
        for (int kh = 0; kh < 4; kh++) {
            int ih = oh * 2 - 1 + kh;
            if ((unsigned)ih < 32u) {
                #pragma unroll
                for (int kw = 0; kw < 4; kw++) {
                    int iw = ow * 2 - 1 + kw;
                    if ((unsigned)iw < 32u)
                        acc += xp[ih * 32 + iw] * sw[ic * 16 + kh * 4 + kw];
                }
            }
        }
    }
    g_z1[(b * C1 + oc) * 256 + t] = fmaxf(acc, 0.0f);
}

// ---------------------------------------------------------------------------
// conv2: z1 (B,32,16,16) -> z2 (B,64,8,8), k=4, stride=2, pad=1, relu
// grid = dim3(B, 16); each block: 4 output channels x 64 pixels = 256 threads
// z1[b] (32KB) and the 4 channels' weights (8KB) staged in smem
// ---------------------------------------------------------------------------
__global__ void conv2_kernel(const float* __restrict__ w,
                             const float* __restrict__ bias) {
    __shared__ float sz[C1 * 256];       // 32 KB
    __shared__ float sw[4 * C1 * 16];    // 8 KB

    int b   = blockIdx.x;
    int ocg = blockIdx.y;                // 0..15
    int t   = threadIdx.x;

    for (int i = t; i < C1 * 256; i += 256) sz[i] = g_z1[b * C1 * 256 + i];
    for (int i = t; i < 4 * C1 * 16; i += 256) sw[i] = w[ocg * 4 * C1 * 16 + i];
    __syncthreads();

    int ocl = t >> 6;                    // 0..3
    int oc  = ocg * 4 + ocl;
    int pix = t & 63;
    int oh = pix >> 3, ow = pix & 7;

    const float* wp = sw + ocl * C1 * 16;
    float acc = bias[oc];
    #pragma unroll 4
    for (int ic = 0; ic < C1; ic++) {
        const float* zp  = sz + ic * 256;
        const float* wpp = wp + ic * 16;
        #pragma unroll
        for (int kh = 0; kh < 4; kh++) {
            int ih = oh * 2 - 1 + kh;
            if ((unsigned)ih < 16u) {
                #pragma unroll
                for (int kw = 0; kw < 4; kw++) {
                    int iw = ow * 2 - 1 + kw;
                    if ((unsigned)iw < 16u)
                        acc += zp[ih * 16 + iw] * wpp[kh * 4 + kw];
                }
            }
        }
    }
    g_z2[(b * C2 + oc) * 64 + pix] = fmaxf(acc, 0.0f);
}

// ---------------------------------------------------------------------------
// V = lookup (512,64) @ Wv (64,64)
// grid = 128 blocks x 256 threads; one output element per thread; Wv in smem
// ---------------------------------------------------------------------------
__global__ void vmat_kernel(const float* __restrict__ lookup,
                            const float* __restrict__ Wv) {
    __shared__ float swv[64 * 64];       // 16 KB
    int t = threadIdx.x;
    for (int i = t; i < 4096; i += 256) swv[i] = Wv[i];
    __syncthreads();

    int idx = blockIdx.x * 256 + t;
    int m = idx >> 6, d = idx & 63;
    const float* L = lookup + m * 64;
    float acc = 0.0f;
    #pragma unroll 8
    for (int k = 0; k < 64; k++) acc += L[k] * swv[k * 64 + d];
    g_V[idx] = acc;
}

// ---------------------------------------------------------------------------
// Hopfield retrieve, one block per token (b, n):
//   scores_m = <z2[b,:,n], lookup[m,:]> / 8       (warp per memory row)
//   p = softmax(scores)                            (block reduce over 512)
//   pre = p @ V                                    (4 m-groups x 64 dims)
//   out[b, e, n] = <pre, Wo[:, e]>                 (4 d-groups x 64 dims)
// grid = B*64 = 256 blocks, 256 threads
// ---------------------------------------------------------------------------
__global__ void attn_kernel(const float* __restrict__ lookup,
                            const float* __restrict__ Wo,
                            float* __restrict__ out) {
    __shared__ float st[64];
    __shared__ float ss[MROWS];
    __shared__ float red1[8];
    __shared__ float red2[8];
    __shared__ float part[256];
    __shared__ float pre[64];

    int bn = blockIdx.x;
    int b = bn >> 6, n = bn & 63;
    int tid  = threadIdx.x;
    int lane = tid & 31;
    int warp = tid >> 5;

    if (tid < 64) st[tid] = g_z2[(b * C2 + tid) * 64 + n];
    __syncthreads();

    // scores: one warp per memory row
    for (int m = warp; m < MROWS; m += 8) {
        const float* L = lookup + m * 64;
        float v = st[lane] * L[lane] + st[lane + 32] * L[lane + 32];
        #pragma unroll
        for (int o = 16; o; o >>= 1) v += __shfl_xor_sync(0xffffffffu, v, o);
        if (lane == 0) ss[m] = v * 0.125f;   // 1/sqrt(64)
    }
    __syncthreads();

    // block max over 512
    float mx = -1e30f;
    #pragma unroll
    for (int m = tid; m < MROWS; m += 256) mx = fmaxf(mx, ss[m]);
    #pragma unroll
    for (int o = 16; o; o >>= 1) mx = fmaxf(mx, __shfl_xor_sync(0xffffffffu, mx, o));
    if (lane == 0) red1[warp] = mx;
    __syncthreads();
    mx = red1[0];
    #pragma unroll
    for (int i = 1; i < 8; i++) mx = fmaxf(mx, red1[i]);

    // exp + block sum
    float sum = 0.0f;
    #pragma unroll
    for (int m = tid; m < MROWS; m += 256) {
        float e = __expf(ss[m] - mx);
        ss[m] = e;
        sum += e;
    }
    #pragma unroll
    for (int o = 16; o; o >>= 1) sum += __shfl_xor_sync(0xffffffffu, sum, o);
    if (lane == 0) red2[warp] = sum;
    __syncthreads();                      // ss writes + red2 now visible
    float total = red2[0];
    #pragma unroll
    for (int i = 1; i < 8; i++) total += red2[i];
    float inv = __frcp_rn(total);

    // pre[d] = (sum_m p_m * V[m][d])   -- 4 m-groups of 128, thread = (g, d)
    int g = tid >> 6;
    int d = tid & 63;
    float acc = 0.0f;
    int m0 = g * 128;
    #pragma unroll 4
    for (int m = m0; m < m0 + 128; m++) acc += ss[m] * g_V[m * 64 + d];
    part[tid] = acc;
    __syncthreads();
    if (tid < 64)
        pre[tid] = (part[tid] + part[tid + 64] + part[tid + 128] + part[tid + 192]) * inv;
    __syncthreads();

    // outf[e] = sum_d pre[d] * Wo[d][e]  -- 4 d-groups of 16, thread = (g, e)
    float acc2 = 0.0f;
    int d0 = g * 16;
    #pragma unroll
    for (int dd = d0; dd < d0 + 16; dd++) acc2 += pre[dd] * Wo[dd * 64 + d];
    part[tid] = acc2;
    __syncthreads();
    if (tid < 64)
        out[b * (C2 * 64) + tid * 64 + n] =
            part[tid] + part[tid + 64] + part[tid + 128] + part[tid + 192];
}

// ---------------------------------------------------------------------------
extern "C" void kernel_launch(void* const* d_in, const int* in_sizes, int n_in,
                              void* d_out, int out_size) {
    const float* x       = (const float*)d_in[0];
    const float* conv1_w = (const float*)d_in[1];
    const float* conv1_b = (const float*)d_in[2];
    const float* conv2_w = (const float*)d_in[3];
    const float* conv2_b = (const float*)d_in[4];
    const float* lookup  = (const float*)d_in[5];
    const float* Wv      = (const float*)d_in[6];
    const float* Wo      = (const float*)d_in[7];
    float* out = (float*)d_out;

    conv1_kernel<<<BATCH * C1, 256>>>(x, conv1_w, conv1_b);
    conv2_kernel<<<dim3(BATCH, 16), 256>>>(conv2_w, conv2_b);
    vmat_kernel<<<(MROWS * C2) / 256, 256>>>(lookup, Wv);
    attn_kernel<<<BATCH * 64, 256>>>(lookup, Wo, out);
}

// round 2
// speedup vs baseline: 1.1952x; 1.1952x over previous
#include <cuda_runtime.h>

#define BATCH 4
#define CIN   3
#define C1    32
#define C2    64
#define MROWS 512

// Intermediates (no allocation allowed -> __device__ globals)
__device__ float g_z1 [BATCH * C1 * 16 * 16];   // conv1 output, relu'd
__device__ float g_z2t[BATCH * 64 * C2];        // conv2 output, token-major: [b][pix][oc]
__device__ __align__(16) float g_V[MROWS * C2]; // lookup @ Wv

// ---------------------------------------------------------------------------
// conv1: x (B,3,32,32) -> z1 (B,32,16,16), k=4, stride=2, pad=1, relu
// ---------------------------------------------------------------------------
__global__ void __launch_bounds__(256) conv1_kernel(const float* __restrict__ x,
                             const float* __restrict__ w,
                             const float* __restrict__ bias) {
    int blk = blockIdx.x;
    int b  = blk / C1;
    int oc = blk % C1;
    int t  = threadIdx.x;            // 0..255
    int oh = t >> 4, ow = t & 15;

    __shared__ float sw[CIN * 16];
    if (t < CIN * 16) sw[t] = w[oc * CIN * 16 + t];
    __syncthreads();

    float acc = bias[oc];
    #pragma unroll
    for (int ic = 0; ic < CIN; ic++) {
        const float* xp = x + (b * CIN + ic) * 32 * 32;
        #pragma unroll
        for (int kh = 0; kh < 4; kh++) {
            int ih = oh * 2 - 1 + kh;
            if ((unsigned)ih < 32u) {
                #pragma unroll
                for (int kw = 0; kw < 4; kw++) {
                    int iw = ow * 2 - 1 + kw;
                    if ((unsigned)iw < 32u)
                        acc += xp[ih * 32 + iw] * sw[ic * 16 + kh * 4 + kw];
                }
            }
        }
    }
    g_z1[(b * C1 + oc) * 256 + t] = fmaxf(acc, 0.0f);
}

// ---------------------------------------------------------------------------
// conv2: z1 (B,32,16,16) -> z2 (B,64,8,8), k=4, stride=2, pad=1, relu
// Stores TOKEN-MAJOR: g_z2t[b][pix][oc] so attn's token load is coalesced.
// grid = dim3(B, 16); 4 output channels x 64 pixels = 256 threads
// ---------------------------------------------------------------------------
__global__ void __launch_bounds__(256) conv2_kernel(const float* __restrict__ w,
                             const float* __restrict__ bias) {
    __shared__ float sz[C1 * 256];       // 32 KB
    __shared__ float sw[4 * C1 * 16];    // 8 KB

    int b   = blockIdx.x;
    int ocg = blockIdx.y;                // 0..15
    int t   = threadIdx.x;

    for (int i = t; i < C1 * 256; i += 256) sz[i] = g_z1[b * C1 * 256 + i];
    for (int i = t; i < 4 * C1 * 16; i += 256) sw[i] = w[ocg * 4 * C1 * 16 + i];
    __syncthreads();

    int ocl = t >> 6;                    // 0..3
    int oc  = ocg * 4 + ocl;
    int pix = t & 63;
    int oh = pix >> 3, ow = pix & 7;

    const float* wp = sw + ocl * C1 * 16;
    float acc = bias[oc];
    #pragma unroll 4
    for (int ic = 0; ic < C1; ic++) {
        const float* zp  = sz + ic * 256;
        const float* wpp = wp + ic * 16;
        #pragma unroll
        for (int kh = 0; kh < 4; kh++) {
            int ih = oh * 2 - 1 + kh;
            if ((unsigned)ih < 16u) {
                #pragma unroll
                for (int kw = 0; kw < 4; kw++) {
                    int iw = ow * 2 - 1 + kw;
                    if ((unsigned)iw < 16u)
                        acc += zp[ih * 16 + iw] * wpp[kh * 4 + kw];
                }
            }
        }
    }
    g_z2t[(b * 64 + pix) * C2 + oc] = fmaxf(acc, 0.0f);
}

// ---------------------------------------------------------------------------
// V = lookup (512,64) @ Wv (64,64)
// ---------------------------------------------------------------------------
__global__ void __launch_bounds__(256) vmat_kernel(const float* __restrict__ lookup,
                            const float* __restrict__ Wv) {
    __shared__ float swv[64 * 64];       // 16 KB
    int t = threadIdx.x;
    for (int i = t; i < 4096; i += 256) swv[i] = Wv[i];
    __syncthreads();

    int idx = blockIdx.x * 256 + t;
    int m = idx >> 6, d = idx & 63;
    const float4* L4 = (const float4*)(lookup + m * 64);
    float acc = 0.0f;
    #pragma unroll
    for (int k4 = 0; k4 < 16; k4++) {
        float4 l = L4[k4];
        int k = k4 * 4;
        acc += l.x * swv[(k + 0) * 64 + d];
        acc += l.y * swv[(k + 1) * 64 + d];
        acc += l.z * swv[(k + 2) * 64 + d];
        acc += l.w * swv[(k + 3) * 64 + d];
    }
    g_V[idx] = acc;
}

// ---------------------------------------------------------------------------
// Hopfield retrieve, one block per token (b, n), 256 threads:
//   Phase 1: thread t computes scores for rows t and t+256 (full 64-dot,
//            float4 loads, no shuffles)
//   Phase 2: block softmax over 512
//   Phase 3: pre = p @ V  with (16 m-groups x 16 d-quads), float4 V loads
//   Phase 4: out = pre @ Wo
// ---------------------------------------------------------------------------
__global__ void __launch_bounds__(256) attn_kernel(const float* __restrict__ lookup,
                            const float* __restrict__ Wo,
                            float* __restrict__ out) {
    __shared__ __align__(16) float st[64];
    __shared__ float ss[MROWS];
    __shared__ float red[16];
    __shared__ __align__(16) float4 part4[256];   // 4 KB scratch
    __shared__ float pre[64];

    int bn = blockIdx.x;
    int b = bn >> 6, n = bn & 63;
    int tid  = threadIdx.x;
    int lane = tid & 31;
    int warp = tid >> 5;

    // token (coalesced from token-major z2)
    if (tid < 64) st[tid] = g_z2t[(b * 64 + n) * C2 + tid];
    __syncthreads();

    // ---- scores: rows tid and tid+256, register dot against smem token ----
    const float4* st4 = (const float4*)st;
    #pragma unroll
    for (int r = 0; r < 2; r++) {
        int m = tid + r * 256;
        const float4* L4 = (const float4*)(lookup + m * 64);
        float a0 = 0.f, a1 = 0.f, a2 = 0.f, a3 = 0.f;
        #pragma unroll
        for (int k = 0; k < 16; k += 4) {
            float4 l0 = L4[k + 0], l1 = L4[k + 1], l2 = L4[k + 2], l3 = L4[k + 3];
            float4 s0 = st4[k + 0], s1 = st4[k + 1], s2 = st4[k + 2], s3 = st4[k + 3];
            a0 += l0.x * s0.x + l0.y * s0.y + l0.z * s0.z + l0.w * s0.w;
            a1 += l1.x * s1.x + l1.y * s1.y + l1.z * s1.z + l1.w * s1.w;
            a2 += l2.x * s2.x + l2.y * s2.y + l2.z * s2.z + l2.w * s2.w;
            a3 += l3.x * s3.x + l3.y * s3.y + l3.z * s3.z + l3.w * s3.w;
        }
        ss[m] = (a0 + a1 + a2 + a3) * 0.125f;   // 1/sqrt(64)
    }
    __syncthreads();

    // ---- softmax: block max ----
    float mx = fmaxf(ss[tid], ss[tid + 256]);
    #pragma unroll
    for (int o = 16; o; o >>= 1) mx = fmaxf(mx, __shfl_xor_sync(0xffffffffu, mx, o));
    if (lane == 0) red[warp] = mx;
    __syncthreads();
    mx = red[0];
    #pragma unroll
    for (int i = 1; i < 8; i++) mx = fmaxf(mx, red[i]);

    // ---- exp + block sum (unnormalized p left in ss) ----
    float e0 = __expf(ss[tid]       - mx);
    float e1 = __expf(ss[tid + 256] - mx);
    ss[tid]       = e0;
    ss[tid + 256] = e1;
    float sum = e0 + e1;
    #pragma unroll
    for (int o = 16; o; o >>= 1) sum += __shfl_xor_sync(0xffffffffu, sum, o);
    if (lane == 0) red[8 + warp] = sum;
    __syncthreads();                      // covers ss writes + red
    float total = red[8];
    #pragma unroll
    for (int i = 9; i < 16; i++) total += red[i];
    float inv = __frcp_rn(total);

    // ---- pre[d] = inv * sum_m p_m V[m][d] ; thread = (g:0..15, q:0..15) ----
    int g = tid >> 4, q = tid & 15;
    const float4* V4 = (const float4*)g_V;
    float4 acc = make_float4(0.f, 0.f, 0.f, 0.f);
    int m0 = g * 32;
    #pragma unroll 8
    for (int m = m0; m < m0 + 32; m++) {
        float p = ss[m];
        float4 v = V4[m * 16 + q];
        acc.x += p * v.x; acc.y += p * v.y; acc.z += p * v.z; acc.w += p * v.w;
    }
    part4[g * 16 + q] = acc;
    __syncthreads();
    const float* partf = (const float*)part4;   // [g][d] view, d = q*4+c
    if (tid < 64) {
        float s = 0.f;
        #pragma unroll
        for (int gg = 0; gg < 16; gg++) s += partf[gg * 64 + tid];
        pre[tid] = s * inv;
    }
    __syncthreads();

    // ---- out[b, e, n] = sum_d pre[d] * Wo[d][e] ; thread = (g2:0..3, e) ----
    int e = tid & 63, g2 = tid >> 6;
    float acc2 = 0.f;
    int d0 = g2 * 16;
    #pragma unroll
    for (int dd = d0; dd < d0 + 16; dd++) acc2 += pre[dd] * Wo[dd * 64 + e];
    float* pf = (float*)part4;
    pf[tid] = acc2;
    __syncthreads();
    if (tid < 64)
        out[b * (C2 * 64) + tid * 64 + n] =
            pf[tid] + pf[tid + 64] + pf[tid + 128] + pf[tid + 192];
}

// ---------------------------------------------------------------------------
extern "C" void kernel_launch(void* const* d_in, const int* in_sizes, int n_in,
                              void* d_out, int out_size) {
    const float* x       = (const float*)d_in[0];
    const float* conv1_w = (const float*)d_in[1];
    const float* conv1_b = (const float*)d_in[2];
    const float* conv2_w = (const float*)d_in[3];
    const float* conv2_b = (const float*)d_in[4];
    const float* lookup  = (const float*)d_in[5];
    const float* Wv      = (const float*)d_in[6];
    const float* Wo      = (const float*)d_in[7];
    float* out = (float*)d_out;

    conv1_kernel<<<BATCH * C1, 256>>>(x, conv1_w, conv1_b);
    conv2_kernel<<<dim3(BATCH, 16), 256>>>(conv2_w, conv2_b);
    vmat_kernel<<<(MROWS * C2) / 256, 256>>>(lookup, Wv);
    attn_kernel<<<BATCH * 64, 256>>>(lookup, Wo, out);
}

// round 3
// speedup vs baseline: 1.9389x; 1.6222x over previous
#include <cuda_runtime.h>

#define BATCH 4
#define CIN   3
#define C1    32
#define C2    64
#define MROWS 512

// Intermediates (no allocation allowed -> __device__ globals)
__device__ float g_z1[BATCH * C1 * 256];         // conv1 output, relu'd: [b][ic][16x16]
__device__ __align__(16) float g_V[MROWS * C2];  // lookup @ Wv

// ---------------------------------------------------------------------------
// K1: block-dispatched fusion of two independent producers.
//   blocks [0,128):   conv1  x (B,3,32,32) -> z1 (B,32,16,16), k4 s2 p1, relu
//   blocks [128,256): V = lookup (512,64) @ Wv (64,64)
// ---------------------------------------------------------------------------
__global__ void __launch_bounds__(256) k1_kernel(const float* __restrict__ x,
                                                 const float* __restrict__ w1,
                                                 const float* __restrict__ b1,
                                                 const float* __restrict__ lookup,
                                                 const float* __restrict__ Wv) {
    int blk = blockIdx.x;
    int t   = threadIdx.x;

    if (blk < 128) {
        // ---- conv1: one block per (b, oc), one thread per output pixel ----
        int b  = blk >> 5;
        int oc = blk & 31;
        __shared__ float sw[CIN * 16];
        if (t < CIN * 16) sw[t] = w1[oc * CIN * 16 + t];
        __syncthreads();

        int oh = t >> 4, ow = t & 15;
        float acc = b1[oc];
        #pragma unroll
        for (int ic = 0; ic < CIN; ic++) {
            const float* xp = x + (b * CIN + ic) * 1024;
            #pragma unroll
            for (int kh = 0; kh < 4; kh++) {
                int ih = oh * 2 - 1 + kh;
                if ((unsigned)ih < 32u) {
                    #pragma unroll
                    for (int kw = 0; kw < 4; kw++) {
                        int iw = ow * 2 - 1 + kw;
                        if ((unsigned)iw < 32u)
                            acc += xp[ih * 32 + iw] * sw[ic * 16 + kh * 4 + kw];
                    }
                }
            }
        }
        g_z1[(b * C1 + oc) * 256 + t] = fmaxf(acc, 0.0f);
    } else {
        // ---- vmat: one output element per thread, Wv staged in smem ----
        __shared__ float swv[64 * 64];
        for (int i = t; i < 4096; i += 256) swv[i] = Wv[i];
        __syncthreads();

        int idx = (blk - 128) * 256 + t;
        int m = idx >> 6, d = idx & 63;
        const float4* L4 = (const float4*)(lookup + m * 64);
        float acc = 0.0f;
        #pragma unroll
        for (int k4 = 0; k4 < 16; k4++) {
            float4 l = L4[k4];
            int k = k4 * 4;
            acc += l.x * swv[(k + 0) * 64 + d];
            acc += l.y * swv[(k + 1) * 64 + d];
            acc += l.z * swv[(k + 2) * 64 + d];
            acc += l.w * swv[(k + 3) * 64 + d];
        }
        g_V[idx] = acc;
    }
}

// ---------------------------------------------------------------------------
// K2: conv2-fused Hopfield retrieve. One block per (b, pixel-pair): 128 blocks,
// 256 threads, TWO tokens per block (adjacent pixels -> shared z1 patch).
//   Prologue: compute z2[b,:,p0] and z2[b,:,p0+1] from g_z1 + conv2 weights.
//   Phase 1:  scores for both tokens (each lookup row loaded once).
//   Phase 2:  dual softmax (independent shuffle chains).
//   Phase 3:  p@V for both tokens (each V quad loaded once).
//   Phase 4:  @Wo, write both output columns.
// ---------------------------------------------------------------------------
__global__ void __launch_bounds__(256) k2_kernel(const float* __restrict__ w2,
                                                 const float* __restrict__ b2,
                                                 const float* __restrict__ lookup,
                                                 const float* __restrict__ Wo,
                                                 float* __restrict__ out) {
    __shared__ __align__(16) float sz[C1 * 32];      // z1 patch: [ic][kh(4)][8 padded]
    __shared__ float zpart[256];
    __shared__ __align__(16) float st[2][64];        // the 2 token vectors
    __shared__ float ss0[MROWS];
    __shared__ float ss1[MROWS];
    __shared__ float red[32];
    __shared__ __align__(16) float4 part[2 * 16 * 16]; // 8 KB
    __shared__ float pre[2][64];
    __shared__ float pf[256];

    int bn   = blockIdx.x;          // 0..127
    int b    = bn >> 5;
    int pair = bn & 31;
    int p0   = pair * 2;            // even pixel; p0 and p0+1 share a row
    int oh   = p0 >> 3, ow0 = p0 & 7;
    int r0   = oh * 2 - 1, c0 = ow0 * 2 - 1;
    int t    = threadIdx.x;
    int lane = t & 31, warp = t >> 5;

    // ---- load zero-padded z1 patch: 32 ic x 4 rows x 6 cols ----
    for (int i = t; i < 768; i += 256) {
        int ic = i / 24, e = i % 24;
        int kh = e / 6, kc = e % 6;
        int ih = r0 + kh, iw = c0 + kc;
        float v = 0.0f;
        if ((unsigned)ih < 16u && (unsigned)iw < 16u)
            v = g_z1[(b * C1 + ic) * 256 + ih * 16 + iw];
        sz[ic * 32 + kh * 8 + kc] = v;
    }
    __syncthreads();

    // ---- conv2 for 2 pixels: 128 outputs, ic split across 2 thread halves ----
    {
        int pix = t & 1, oc = (t >> 1) & 63, half = t >> 7;
        const float4* W4 = (const float4*)(w2 + (oc * C1 + half * 16) * 16);
        int cb = 2 * pix;
        float acc = 0.0f;
        #pragma unroll
        for (int ic = 0; ic < 16; ic++) {
            const float* zp = sz + (half * 16 + ic) * 32 + cb;
            float4 wa = W4[ic * 4 + 0], wb = W4[ic * 4 + 1];
            float4 wc = W4[ic * 4 + 2], wd = W4[ic * 4 + 3];
            acc += zp[0]  * wa.x + zp[1]  * wa.y + zp[2]  * wa.z + zp[3]  * wa.w;
            acc += zp[8]  * wb.x + zp[9]  * wb.y + zp[10] * wb.z + zp[11] * wb.w;
            acc += zp[16] * wc.x + zp[17] * wc.y + zp[18] * wc.z + zp[19] * wc.w;
            acc += zp[24] * wd.x + zp[25] * wd.y + zp[26] * wd.z + zp[27] * wd.w;
        }
        zpart[t] = acc;
    }
    __syncthreads();
    if (t < 128) {
        int pix = t & 1, oc = t >> 1;
        st[pix][oc] = fmaxf(zpart[t] + zpart[t + 128] + b2[oc], 0.0f);
    }
    __syncthreads();

    // ---- scores: thread t handles rows t, t+256; each row dotted w/ 2 tokens ----
    const float4* s40 = (const float4*)st[0];
    const float4* s41 = (const float4*)st[1];
    #pragma unroll
    for (int r = 0; r < 2; r++) {
        int m = t + r * 256;
        const float4* L4 = (const float4*)(lookup + m * 64);
        float a0 = 0.f, a0b = 0.f, a1 = 0.f, a1b = 0.f;
        #pragma unroll
        for (int k = 0; k < 16; k += 2) {
            float4 l0 = L4[k], l1 = L4[k + 1];
            float4 u0 = s40[k], u1 = s40[k + 1];
            float4 v0 = s41[k], v1 = s41[k + 1];
            a0  += l0.x * u0.x + l0.y * u0.y + l0.z * u0.z + l0.w * u0.w;
            a0b += l1.x * u1.x + l1.y * u1.y + l1.z * u1.z + l1.w * u1.w;
            a1  += l0.x * v0.x + l0.y * v0.y + l0.z * v0.z + l0.w * v0.w;
            a1b += l1.x * v1.x + l1.y * v1.y + l1.z * v1.z + l1.w * v1.w;
        }
        ss0[m] = (a0 + a0b) * 0.125f;     // 1/sqrt(64)
        ss1[m] = (a1 + a1b) * 0.125f;
    }
    __syncthreads();

    // ---- dual softmax: max ----
    float m0 = fmaxf(ss0[t], ss0[t + 256]);
    float m1 = fmaxf(ss1[t], ss1[t + 256]);
    #pragma unroll
    for (int o = 16; o; o >>= 1) {
        m0 = fmaxf(m0, __shfl_xor_sync(0xffffffffu, m0, o));
        m1 = fmaxf(m1, __shfl_xor_sync(0xffffffffu, m1, o));
    }
    if (lane == 0) { red[warp] = m0; red[8 + warp] = m1; }
    __syncthreads();
    m0 = red[0]; m1 = red[8];
    #pragma unroll
    for (int i = 1; i < 8; i++) { m0 = fmaxf(m0, red[i]); m1 = fmaxf(m1, red[8 + i]); }

    // ---- exp + sum ----
    float e00 = __expf(ss0[t] - m0),       e01 = __expf(ss0[t + 256] - m0);
    float e10 = __expf(ss1[t] - m1),       e11 = __expf(ss1[t + 256] - m1);
    ss0[t] = e00; ss0[t + 256] = e01;
    ss1[t] = e10; ss1[t + 256] = e11;
    float s0 = e00 + e01, s1 = e10 + e11;
    #pragma unroll
    for (int o = 16; o; o >>= 1) {
        s0 += __shfl_xor_sync(0xffffffffu, s0, o);
        s1 += __shfl_xor_sync(0xffffffffu, s1, o);
    }
    if (lane == 0) { red[16 + warp] = s0; red[24 + warp] = s1; }
    __syncthreads();                     // covers ss writes + red
    float tot0 = red[16], tot1 = red[24];
    #pragma unroll
    for (int i = 1; i < 8; i++) { tot0 += red[16 + i]; tot1 += red[24 + i]; }
    float inv0 = __frcp_rn(tot0), inv1 = __frcp_rn(tot1);

    // ---- p@V: thread = (g: m-group of 32, q: d-quad); V quad loaded once ----
    int g = t >> 4, q = t & 15;
    const float4* V4 = (const float4*)g_V;
    float4 A = make_float4(0.f, 0.f, 0.f, 0.f);
    float4 Bv = make_float4(0.f, 0.f, 0.f, 0.f);
    int mb = g * 32;
    #pragma unroll 8
    for (int m = mb; m < mb + 32; m++) {
        float4 v = V4[m * 16 + q];
        float pa = ss0[m], pb = ss1[m];
        A.x  += pa * v.x; A.y  += pa * v.y; A.z  += pa * v.z; A.w  += pa * v.w;
        Bv.x += pb * v.x; Bv.y += pb * v.y; Bv.z += pb * v.z; Bv.w += pb * v.w;
    }
    part[g * 16 + q]       = A;
    part[256 + g * 16 + q] = Bv;
    __syncthreads();
    if (t < 128) {
        int j = t >> 6, d = t & 63;
        const float* pp = (const float*)(part + j * 256);
        float s = 0.f;
        #pragma unroll
        for (int gg = 0; gg < 16; gg++) s += pp[gg * 64 + d];
        pre[j][d] = s * (j ? inv1 : inv0);
    }
    __syncthreads();

    // ---- @Wo: thread = (half: d-range, j: token, e) ----
    {
        int j = (t >> 6) & 1, half = t >> 7, e = t & 63;
        float acc = 0.f;
        int d0 = half * 32;
        #pragma unroll
        for (int d = d0; d < d0 + 32; d++) acc += pre[j][d] * Wo[d * 64 + e];
        pf[t] = acc;
    }
    __syncthreads();
    if (t < 128) {
        int j = t >> 6, e = t & 63;
        out[b * 4096 + e * 64 + (p0 + j)] = pf[t] + pf[t + 128];
    }
}

// ---------------------------------------------------------------------------
extern "C" void kernel_launch(void* const* d_in, const int* in_sizes, int n_in,
                              void* d_out, int out_size) {
    const float* x       = (const float*)d_in[0];
    const float* conv1_w = (const float*)d_in[1];
    const float* conv1_b = (const float*)d_in[2];
    const float* conv2_w = (const float*)d_in[3];
    const float* conv2_b = (const float*)d_in[4];
    const float* lookup  = (const float*)d_in[5];
    const float* Wv      = (const float*)d_in[6];
    const float* Wo      = (const float*)d_in[7];
    float* out = (float*)d_out;

    k1_kernel<<<256, 256>>>(x, conv1_w, conv1_b, lookup, Wv);
    k2_kernel<<<128, 256>>>(conv2_w, conv2_b, lookup, Wo, out);
}